// round 1
// baseline (speedup 1.0000x reference)
#include <cuda_runtime.h>
#include <math.h>

// ---------------------------------------------------------------------------
// GaussianSplatRenderer3D — B=4, N=32768, H=W=512, kernel k=11 (121 taps)
// Pipeline: zero accumulators -> splat (RED atomics) -> normalize
// Scratch lives in __device__ globals (no allocations, graph-capturable).
// ---------------------------------------------------------------------------

#define KTAP 11
#define MAXPIX (4 * 512 * 512)

static __device__ float4 g_accum[MAXPIX];   // r*a, g*a, b*a, a
static __device__ float  g_accumZ[MAXPIX];  // z*a

__global__ void zero_kernel(int npix) {
    int i = blockIdx.x * blockDim.x + threadIdx.x;
    if (i < npix) {
        g_accum[i]  = make_float4(0.f, 0.f, 0.f, 0.f);
        g_accumZ[i] = 0.f;
    }
}

__global__ void __launch_bounds__(128)
splat_kernel(const float* __restrict__ pos, const float* __restrict__ cov,
             const float* __restrict__ rgb, const float* __restrict__ opa,
             const float* __restrict__ Km,  const float* __restrict__ Rm,
             const float* __restrict__ tv,  int B, int N, int H, int W)
{
    int gid = blockIdx.x * blockDim.x + threadIdx.x;
    if (gid >= B * N) return;
    int b = gid / N;

    const float* Kb = Km + 9 * b;
    const float* Rb = Rm + 9 * b;
    const float* tb = tv + 3 * b;

    float p0 = pos[3 * gid + 0];
    float p1 = pos[3 * gid + 1];
    float p2 = pos[3 * gid + 2];

    // Xc = R @ p + t   (dot as mul/add chain, then + t; no FMA contraction)
    float X = __fadd_rn(__fadd_rn(__fadd_rn(__fmul_rn(Rb[0], p0), __fmul_rn(Rb[1], p1)),
                                  __fmul_rn(Rb[2], p2)), tb[0]);
    float Y = __fadd_rn(__fadd_rn(__fadd_rn(__fmul_rn(Rb[3], p0), __fmul_rn(Rb[4], p1)),
                                  __fmul_rn(Rb[5], p2)), tb[1]);
    float Z = __fadd_rn(__fadd_rn(__fadd_rn(__fmul_rn(Rb[6], p0), __fmul_rn(Rb[7], p1)),
                                  __fmul_rn(Rb[8], p2)), tb[2]);

    float zs = fmaxf(Z, 1e-6f);
    float xs = __fdiv_rn(X, zs);
    float ys = __fdiv_rn(Y, zs);

    // uvh = K @ [xs, ys, 1]
    float u = __fadd_rn(__fadd_rn(__fmul_rn(Kb[0], xs), __fmul_rn(Kb[1], ys)), Kb[2]);
    float v = __fadd_rn(__fadd_rn(__fmul_rn(Kb[3], xs), __fmul_rn(Kb[4], ys)), Kb[5]);
    float fx = Kb[0];
    float fy = Kb[4];

    float sxx = cov[3 * gid + 0];
    float syy = cov[3 * gid + 1];
    float sx = __fdiv_rn(__fmul_rn(__fsqrt_rn(fmaxf(sxx, 1e-9f)), fx), zs);
    float sy = __fdiv_rn(__fmul_rn(__fsqrt_rn(fmaxf(syy, 1e-9f)), fy), zs);

    float o  = opa[gid];
    float cr = rgb[3 * gid + 0];
    float cg = rgb[3 * gid + 1];
    float cb = rgb[3 * gid + 2];

    float isx = __fdiv_rn(1.f, fmaxf(sx, 1e-6f));
    float isy = __fdiv_rn(1.f, fmaxf(sy, 1e-6f));

    // Separable weights and rounded pixel coords per axis
    float wx[KTAP], wy[KTAP];
    int   pxi[KTAP], pyi[KTAP];
#pragma unroll
    for (int i = 0; i < KTAP; ++i) {
        float off = (float)(i - KTAP / 2);
        float gx = __fmul_rn(off, isx);
        float gy = __fmul_rn(off, isy);
        wx[i] = __expf(-0.5f * __fmul_rn(gx, gx));
        wy[i] = __expf(-0.5f * __fmul_rn(gy, gy));
        pxi[i] = __float2int_rn(__fadd_rn(u, __fmul_rn(off, sx)));
        pyi[i] = __float2int_rn(__fadd_rn(v, __fmul_rn(off, sy)));
    }

    int baseb = b * (H * W);
#pragma unroll
    for (int j = 0; j < KTAP; ++j) {
        int py = pyi[j];
        if (py < 0 || py >= H) continue;           // reference adds exact 0 here
        float wo = __fmul_rn(o, wy[j]);
        if (wo == 0.f) continue;                   // exact-0 contribution: skip
        int rowbase = baseb + py * W;
#pragma unroll
        for (int i = 0; i < KTAP; ++i) {
            int px = pxi[i];
            if (px < 0 || px >= W) continue;
            float a = __fmul_rn(wo, wx[i]);
            if (a == 0.f) continue;
            int lin = rowbase + px;
            float4* dst4 = &g_accum[lin];
            float*  dstz = &g_accumZ[lin];
            float va0 = cr * a, va1 = cg * a, va2 = cb * a;
            float vz  = Z * a;
            asm volatile("red.global.add.v4.f32 [%0], {%1, %2, %3, %4};"
                         :: "l"(dst4), "f"(va0), "f"(va1), "f"(va2), "f"(a)
                         : "memory");
            asm volatile("red.global.add.f32 [%0], %1;"
                         :: "l"(dstz), "f"(vz)
                         : "memory");
        }
    }
}

__global__ void normalize_kernel(float* __restrict__ out, int B, int H, int W) {
    int i = blockIdx.x * blockDim.x + threadIdx.x;
    int HW = H * W;
    int npix = B * HW;
    if (i >= npix) return;
    float4 acc = g_accum[i];
    float den = fmaxf(acc.w, 1e-6f);
    int b = i / HW;
    int pix = i - b * HW;
    float* rgbout = out + (size_t)b * 3 * HW + pix;
    rgbout[0]        = __fdiv_rn(acc.x, den);
    rgbout[HW]       = __fdiv_rn(acc.y, den);
    rgbout[2 * HW]   = __fdiv_rn(acc.z, den);
    out[(size_t)B * 3 * HW + (size_t)b * HW + pix] = __fdiv_rn(g_accumZ[i], den);
}

extern "C" void kernel_launch(void* const* d_in, const int* in_sizes, int n_in,
                              void* d_out, int out_size)
{
    const float* pos = (const float*)d_in[0];
    const float* cov = (const float*)d_in[1];
    const float* rgb = (const float*)d_in[2];
    const float* opa = (const float*)d_in[3];
    const float* Km  = (const float*)d_in[4];
    const float* Rm  = (const float*)d_in[5];
    const float* tv  = (const float*)d_in[6];

    int B  = in_sizes[4] / 9;                 // K is [B,3,3]
    int N  = in_sizes[0] / (3 * B);           // pos is [B,N,3]
    int HW = out_size / (4 * B);              // out = [B,3,H,W] rgb + [B,1,H,W] depth
    int W  = (int)(sqrt((double)HW) + 0.5);   // square image
    int H  = HW / W;
    int npix = B * HW;

    zero_kernel<<<(npix + 255) / 256, 256>>>(npix);

    int total = B * N;
    splat_kernel<<<(total + 127) / 128, 128>>>(pos, cov, rgb, opa, Km, Rm, tv, B, N, H, W);

    normalize_kernel<<<(npix + 255) / 256, 256>>>((float*)d_out, B, H, W);
}